// round 1
// baseline (speedup 1.0000x reference)
#include <cuda_runtime.h>

// Shift_14422500180434: 3x3 spatial shift "im2col-lite".
//   x:   [N=32, C=64, H=56, W=56] f32
//   out: [N=32, C*9=576, H=56, W=56] f32
//   out[n, c*9 + 3*dy + dx, h, w] = x[n, c, h+dy-1, w+dx-1]  (zero pad)
//
// Strategy: one thread per (n, c, h, group-of-4 w). Each thread loads the
// 3 relevant input rows (6 floats each: aligned float4 + 2 edge scalars),
// then emits all 9 shifted float4 outputs with coalesced STG.128.
// Write traffic (231 MB) is the binding resource; reads (25.7 MB) live in L1/L2.

#define N_ 32
#define C_ 64
#define H_ 56
#define W_ 56
#define W4_ 14              // W/4
#define PLANE_ (H_ * W_)    // 3136
#define TOTAL_THREADS_ (N_ * C_ * H_ * W4_)   // 1,605,632

__global__ __launch_bounds__(256) void shift_kernel(
    const float* __restrict__ x, float* __restrict__ out)
{
    int t = blockIdx.x * blockDim.x + threadIdx.x;
    if (t >= TOTAL_THREADS_) return;

    int w4 = t % W4_;
    int h  = (t / W4_) % H_;
    int c  = (t / (W4_ * H_)) % C_;
    int n  = t / (W4_ * H_ * C_);
    int w0 = w4 * 4;

    const float* __restrict__ xp = x + ((n * C_ + c) * H_) * (long)W_;

    // rows[r][j]: input floats at (h + r - 1, w0 + j - 1), j = 0..5
    float rows[3][6];
#pragma unroll
    for (int r = 0; r < 3; ++r) {
        int hh = h + r - 1;
        bool hv = ((unsigned)hh < (unsigned)H_);
        float4 v = make_float4(0.f, 0.f, 0.f, 0.f);
        float left = 0.f, right = 0.f;
        if (hv) {
            v = *reinterpret_cast<const float4*>(xp + hh * W_ + w0);
            if (w4 > 0)       left  = xp[hh * W_ + w0 - 1];
            if (w4 < W4_ - 1) right = xp[hh * W_ + w0 + 4];
        }
        rows[r][0] = left;
        rows[r][1] = v.x; rows[r][2] = v.y; rows[r][3] = v.z; rows[r][4] = v.w;
        rows[r][5] = right;
    }

    // Output base for s = 0 at this (n, c, h, w0); planes are PLANE_ apart.
    float* __restrict__ op =
        out + (((long)(n * (C_ * 9) + c * 9)) * H_ + h) * W_ + w0;

#pragma unroll
    for (int dy = 0; dy < 3; ++dy) {
#pragma unroll
        for (int dx = 0; dx < 3; ++dx) {
            float4 o = make_float4(rows[dy][dx],     rows[dy][dx + 1],
                                   rows[dy][dx + 2], rows[dy][dx + 3]);
            *reinterpret_cast<float4*>(op + (long)(dy * 3 + dx) * PLANE_) = o;
        }
    }
}

extern "C" void kernel_launch(void* const* d_in, const int* in_sizes, int n_in,
                              void* d_out, int out_size)
{
    const float* x = (const float*)d_in[0];
    float* out = (float*)d_out;
    const int threads = 256;
    const int blocks = (TOTAL_THREADS_ + threads - 1) / threads;  // 6272
    shift_kernel<<<blocks, threads>>>(x, out);
}

// round 2
// speedup vs baseline: 1.1107x; 1.1107x over previous
#include <cuda_runtime.h>

// Shift_14422500180434: 3x3 spatial shift "im2col-lite".
//   x:   [N=32, C=64, H=56, W=56] f32
//   out: [N=32, C*9=576, H=56, W=56] f32
//   out[n, c*9 + 3*dy + dx, h, w] = x[n, c, h+dy-1, w+dx-1]  (zero pad)
//
// R2 changes vs R1 (43.3us, DRAM 63.8%):
//  - __stcs streaming stores: output is write-once, keep it out of L2's way.
//  - per-dy row streaming: only 6 row floats live at a time -> fewer regs,
//    higher occupancy, more stores in flight.
//  - exact grid (6272*256 == total threads): no bounds guard.

#define N_ 32
#define C_ 64
#define H_ 56
#define W_ 56
#define W4_ 14              // W/4
#define PLANE_ (H_ * W_)    // 3136
#define TOTAL_THREADS_ (N_ * C_ * H_ * W4_)   // 1,605,632 = 6272 * 256

__global__ __launch_bounds__(256) void shift_kernel(
    const float* __restrict__ x, float* __restrict__ out)
{
    int t = blockIdx.x * blockDim.x + threadIdx.x;

    int w4 = t % W4_;
    int h  = (t / W4_) % H_;
    int c  = (t / (W4_ * H_)) % C_;
    int n  = t / (W4_ * H_ * C_);
    int w0 = w4 * 4;

    const float* __restrict__ xp = x + ((n * C_ + c) * H_) * (long)W_ + w0;

    // Output base for shift s=0 at this (n, c, h, w0); planes are PLANE_ apart.
    float* __restrict__ op =
        out + (((long)(n * (C_ * 9) + c * 9)) * H_ + h) * W_ + w0;

#pragma unroll
    for (int dy = 0; dy < 3; ++dy) {
        int hh = h + dy - 1;
        bool hv = ((unsigned)hh < (unsigned)H_);

        // row[j]: input float at (hh, w0 + j - 1), j = 0..5 (zero outside)
        float4 v = make_float4(0.f, 0.f, 0.f, 0.f);
        float left = 0.f, right = 0.f;
        if (hv) {
            const float* rp = xp + hh * W_;
            v = *reinterpret_cast<const float4*>(rp);
            if (w4 > 0)       left  = rp[-1];
            if (w4 < W4_ - 1) right = rp[4];
        }
        float r0 = left, r1 = v.x, r2 = v.y, r3 = v.z, r4 = v.w, r5 = right;

        float* o = op + (long)(dy * 3) * PLANE_;
        __stcs(reinterpret_cast<float4*>(o),
               make_float4(r0, r1, r2, r3));
        __stcs(reinterpret_cast<float4*>(o + PLANE_),
               make_float4(r1, r2, r3, r4));
        __stcs(reinterpret_cast<float4*>(o + 2 * PLANE_),
               make_float4(r2, r3, r4, r5));
    }
}

extern "C" void kernel_launch(void* const* d_in, const int* in_sizes, int n_in,
                              void* d_out, int out_size)
{
    const float* x = (const float*)d_in[0];
    float* out = (float*)d_out;
    const int threads = 256;
    const int blocks = TOTAL_THREADS_ / threads;  // 6272, exact
    shift_kernel<<<blocks, threads>>>(x, out);
}